// round 2
// baseline (speedup 1.0000x reference)
#include <cuda_runtime.h>
#include <cuda_bf16.h>

#define FM        64
#define MAXV      100000
#define MAXC      50000
#define MAXNNZ    2000000
#define OUTB      16

typedef unsigned long long u64;

// ---------------- packed f32x2 helpers (Blackwell FFMA2) -------------------
__device__ __forceinline__ u64 pk2(float x) {
    u64 r; asm("mov.b64 %0, {%1, %1};" : "=l"(r) : "f"(x)); return r;
}
__device__ __forceinline__ u64 f2fma(u64 a, u64 b, u64 c) {
    u64 d; asm("fma.rn.f32x2 %0, %1, %2, %3;" : "=l"(d) : "l"(a), "l"(b), "l"(c)); return d;
}
__device__ __forceinline__ float2 up2(u64 a) {
    float2 f; asm("mov.b64 {%0, %1}, %2;" : "=f"(f.x), "=f"(f.y) : "l"(a)); return f;
}

// ---------------- scratch (static device globals; no runtime alloc) --------
__device__ float g_vars[MAXV * FM];
__device__ float g_cons[MAXC * FM];
__device__ float g_v2c [MAXC * FM];
__device__ float g_c2v [MAXV * FM];

__device__ int   g_cntC[MAXC];
__device__ int   g_cntV[MAXV];
__device__ int   g_offC[MAXC + 1];
__device__ int   g_offV[MAXV + 1];
__device__ int   g_curC[MAXC];
__device__ int   g_curV[MAXV];

__device__ int   g_cscRow[MAXNNZ];
__device__ float g_cscVal[MAXNNZ];
__device__ int   g_csrCol[MAXNNZ];
__device__ float g_csrVal[MAXNNZ];

// ---------------- CSR/CSC build --------------------------------------------
__global__ void zero_counts_kernel(int nC, int nV) {
    int i = blockIdx.x * blockDim.x + threadIdx.x;
    if (i < nC) g_cntC[i] = 0;
    if (i < nV) g_cntV[i] = 0;
}

__global__ void hist_kernel(const int* __restrict__ row, const int* __restrict__ col, int nnz) {
    int base = blockIdx.x * blockDim.x * 4 + threadIdx.x;
#pragma unroll
    for (int j = 0; j < 4; j++) {
        int e = base + j * blockDim.x;
        if (e < nnz) {
            atomicAdd(&g_cntC[col[e]], 1);
            atomicAdd(&g_cntV[row[e]], 1);
        }
    }
}

__global__ void scan_kernel(int nC, int nV) {
    const int* cnt; int* off; int* cur; int n;
    if (blockIdx.x == 0) { cnt = g_cntC; off = g_offC; cur = g_curC; n = nC; }
    else                 { cnt = g_cntV; off = g_offV; cur = g_curV; n = nV; }

    __shared__ int part[1024];
    int t = threadIdx.x;
    int chunk = (n + 1023) / 1024;
    int beg = t * chunk;
    int end = min(n, beg + chunk);

    int s = 0;
    for (int i = beg; i < end; i++) s += cnt[i];
    part[t] = s;
    __syncthreads();
    for (int d = 1; d < 1024; d <<= 1) {
        int v = (t >= d) ? part[t - d] : 0;
        __syncthreads();
        part[t] += v;
        __syncthreads();
    }
    int run = (t == 0) ? 0 : part[t - 1];
    for (int i = beg; i < end; i++) {
        off[i] = run; cur[i] = run;
        run += cnt[i];
    }
    if (t == 1023) off[n] = part[1023];
}

__global__ void fill_kernel(const int* __restrict__ row, const int* __restrict__ col,
                            const float* __restrict__ av, int nnz) {
    int base = blockIdx.x * blockDim.x * 4 + threadIdx.x;
#pragma unroll
    for (int j = 0; j < 4; j++) {
        int e = base + j * blockDim.x;
        if (e < nnz) {
            int r = row[e], c = col[e];
            float v = fabsf(av[e]);
            int p = atomicAdd(&g_curC[c], 1);
            g_cscRow[p] = r; g_cscVal[p] = v;
            int q = atomicAdd(&g_curV[r], 1);
            g_csrCol[q] = c; g_csrVal[q] = v;
        }
    }
}

__global__ void init_vars_kernel(int n) {
    int i = blockIdx.x * blockDim.x + threadIdx.x;
    if (i < n) g_vars[i] = 1.0f;
}

// ---------------- segment gather-reduce (warp per segment) -----------------
__global__ void seg_gather_kernel(const int* __restrict__ offs,
                                  const int* __restrict__ idxArr,
                                  const float* __restrict__ valArr,
                                  const float* __restrict__ srcF,
                                  float* __restrict__ dstF, int nseg) {
    int warp = threadIdx.x >> 5;
    int lane = threadIdx.x & 31;
    int seg  = blockIdx.x * (blockDim.x >> 5) + warp;
    if (seg >= nseg) return;

    int s = offs[seg], e = offs[seg + 1];
    u64 acc = 0;
    int p = s;
    for (; p + 4 <= e; p += 4) {
        int   i0 = idxArr[p + 0], i1 = idxArr[p + 1], i2 = idxArr[p + 2], i3 = idxArr[p + 3];
        float v0 = valArr[p + 0], v1 = valArr[p + 1], v2 = valArr[p + 2], v3 = valArr[p + 3];
        u64 f0 = *(const u64*)&srcF[(size_t)i0 * FM + 2 * lane];
        u64 f1 = *(const u64*)&srcF[(size_t)i1 * FM + 2 * lane];
        u64 f2 = *(const u64*)&srcF[(size_t)i2 * FM + 2 * lane];
        u64 f3 = *(const u64*)&srcF[(size_t)i3 * FM + 2 * lane];
        acc = f2fma(pk2(v0), f0, acc);
        acc = f2fma(pk2(v1), f1, acc);
        acc = f2fma(pk2(v2), f2, acc);
        acc = f2fma(pk2(v3), f3, acc);
    }
    for (; p < e; p++) {
        int   i0 = idxArr[p];
        float v0 = valArr[p];
        u64 f0 = *(const u64*)&srcF[(size_t)i0 * FM + 2 * lane];
        acc = f2fma(pk2(v0), f0, acc);
    }
    *(u64*)&dstF[(size_t)seg * FM + 2 * lane] = acc;
}

// ---------------- MLP layer-2 (128 -> 64), packed FFMA2 --------------------
__device__ __forceinline__ void mlp_layer2_64(const float* sb,
                                              const float* __restrict__ W2,
                                              const float* __restrict__ b2,
                                              float* __restrict__ outp,
                                              int row0, int rows, int lane) {
    u64 acc[4] = {0, 0, 0, 0};

    for (int k = 0; k < 128; k += 4) {
        float4 hv[4];
#pragma unroll
        for (int r = 0; r < 4; r++) hv[r] = *(const float4*)&sb[r * 128 + k];
#pragma unroll
        for (int kk = 0; kk < 4; kk++) {
            u64 w = *(const u64*)&W2[(k + kk) * 64 + 2 * lane];
#pragma unroll
            for (int r = 0; r < 4; r++) {
                acc[r] = f2fma(pk2(((const float*)&hv[r])[kk]), w, acc[r]);
            }
        }
    }
    float2 bb = *(const float2*)&b2[2 * lane];
#pragma unroll
    for (int r = 0; r < 4; r++) {
        if (row0 + r < rows) {
            float2 a = up2(acc[r]);
            *(float2*)&outp[(size_t)(row0 + r) * 64 + 2 * lane] =
                make_float2(a.x + bb.x, a.y + bb.y);
        }
    }
}

// ---------------- main MLP: concat(inA[64], inB[64]) -> 128(relu) -> 64 ----
__global__ void __launch_bounds__(256) mlp128_kernel(
                              const float* __restrict__ inA,
                              const float* __restrict__ inB,
                              float* __restrict__ outp,
                              const float* __restrict__ W1, const float* __restrict__ b1,
                              const float* __restrict__ W2, const float* __restrict__ b2,
                              int rows) {
    __shared__ float sbuf[8][512];
    int warp = threadIdx.x >> 5;
    int lane = threadIdx.x & 31;
    int row0 = (blockIdx.x * 8 + warp) * 4;
    if (row0 >= rows) return;
    float* sb = sbuf[warp];

#pragma unroll
    for (int r = 0; r < 4; r++) {
        int row = min(row0 + r, rows - 1);
        float4 v;
        if (lane < 16) v = *(const float4*)&inA[(size_t)row * 64 + lane * 4];
        else           v = *(const float4*)&inB[(size_t)row * 64 + (lane - 16) * 4];
        *(float4*)&sb[r * 128 + lane * 4] = v;
    }
    __syncwarp();

    // layer 1: lane computes hidden j = 4*lane..4*lane+3 as 2 packed pairs
    u64 acc[4][2];
#pragma unroll
    for (int r = 0; r < 4; r++) { acc[r][0] = 0; acc[r][1] = 0; }

    for (int k = 0; k < 128; k += 4) {
        float4 xv[4];
#pragma unroll
        for (int r = 0; r < 4; r++) xv[r] = *(const float4*)&sb[r * 128 + k];
#pragma unroll
        for (int kk = 0; kk < 4; kk++) {
            ulonglong2 w = *(const ulonglong2*)&W1[(k + kk) * 128 + 4 * lane];
#pragma unroll
            for (int r = 0; r < 4; r++) {
                u64 x2 = pk2(((const float*)&xv[r])[kk]);
                acc[r][0] = f2fma(x2, w.x, acc[r][0]);
                acc[r][1] = f2fma(x2, w.y, acc[r][1]);
            }
        }
    }
    float4 bb = *(const float4*)&b1[4 * lane];
    __syncwarp();
#pragma unroll
    for (int r = 0; r < 4; r++) {
        float2 lo = up2(acc[r][0]);
        float2 hi = up2(acc[r][1]);
        float4 h;
        h.x = fmaxf(lo.x + bb.x, 0.f);
        h.y = fmaxf(lo.y + bb.y, 0.f);
        h.z = fmaxf(hi.x + bb.z, 0.f);
        h.w = fmaxf(hi.y + bb.w, 0.f);
        *(float4*)&sb[r * 128 + 4 * lane] = h;
    }
    __syncwarp();

    mlp_layer2_64(sb, W2, b2, outp, row0, rows, lane);
}

// ---------------- prepare_cond: scalar -> 128(relu) -> 64 ------------------
__global__ void __launch_bounds__(256) prep_kernel(
                            const float* __restrict__ cond,
                            const float* __restrict__ w1, const float* __restrict__ b1,
                            const float* __restrict__ w2, const float* __restrict__ b2,
                            int rows) {
    __shared__ float sbuf[8][512];
    int warp = threadIdx.x >> 5;
    int lane = threadIdx.x & 31;
    int row0 = (blockIdx.x * 8 + warp) * 4;
    if (row0 >= rows) return;
    float* sb = sbuf[warp];

    float4 w = *(const float4*)&w1[4 * lane];
    float4 b = *(const float4*)&b1[4 * lane];
#pragma unroll
    for (int r = 0; r < 4; r++) {
        int row = min(row0 + r, rows - 1);
        float c = cond[row];
        float4 h;
        h.x = fmaxf(c * w.x + b.x, 0.f);
        h.y = fmaxf(c * w.y + b.y, 0.f);
        h.z = fmaxf(c * w.z + b.z, 0.f);
        h.w = fmaxf(c * w.w + b.w, 0.f);
        *(float4*)&sb[r * 128 + 4 * lane] = h;
    }
    __syncwarp();
    mlp_layer2_64(sb, w2, b2, g_cons, row0, rows, lane);
}

// ---------------- output: 64 -> 128(relu) -> 16 + sigmoid ------------------
__global__ void __launch_bounds__(256) out_kernel(
                           const float* __restrict__ W1, const float* __restrict__ b1,
                           const float* __restrict__ W2, const float* __restrict__ b2,
                           float* __restrict__ outp, int rows) {
    __shared__ float sbuf[8][512];
    int warp = threadIdx.x >> 5;
    int lane = threadIdx.x & 31;
    int row0 = (blockIdx.x * 8 + warp) * 4;
    if (row0 >= rows) return;
    float* sb = sbuf[warp];

#pragma unroll
    for (int r = 0; r < 4; r++) {
        int row = min(row0 + r, rows - 1);
        float2 v = *(const float2*)&g_vars[(size_t)row * 64 + 2 * lane];
        *(float2*)&sb[r * 128 + 2 * lane] = v;
    }
    __syncwarp();

    // layer 1 (64 -> 128): packed FFMA2
    u64 acc[4][2];
#pragma unroll
    for (int r = 0; r < 4; r++) { acc[r][0] = 0; acc[r][1] = 0; }
    for (int k = 0; k < 64; k += 4) {
        float4 xv[4];
#pragma unroll
        for (int r = 0; r < 4; r++) xv[r] = *(const float4*)&sb[r * 128 + k];
#pragma unroll
        for (int kk = 0; kk < 4; kk++) {
            ulonglong2 w = *(const ulonglong2*)&W1[(k + kk) * 128 + 4 * lane];
#pragma unroll
            for (int r = 0; r < 4; r++) {
                u64 x2 = pk2(((const float*)&xv[r])[kk]);
                acc[r][0] = f2fma(x2, w.x, acc[r][0]);
                acc[r][1] = f2fma(x2, w.y, acc[r][1]);
            }
        }
    }
    float4 bb = *(const float4*)&b1[4 * lane];
    __syncwarp();
#pragma unroll
    for (int r = 0; r < 4; r++) {
        float2 lo = up2(acc[r][0]);
        float2 hi = up2(acc[r][1]);
        float4 h;
        h.x = fmaxf(lo.x + bb.x, 0.f);
        h.y = fmaxf(lo.y + bb.y, 0.f);
        h.z = fmaxf(hi.x + bb.z, 0.f);
        h.w = fmaxf(hi.y + bb.w, 0.f);
        *(float4*)&sb[r * 128 + 4 * lane] = h;
    }
    __syncwarp();

    // layer 2 (128 -> 16): lanes split over (j, row-halves)
    int j = lane & 15;
    int half = lane >> 4;
    float a0 = 0.f, a1 = 0.f;
#pragma unroll 4
    for (int k = 0; k < 128; k++) {
        float w = W2[k * 16 + j];
        a0 += sb[half * 128 + k] * w;
        a1 += sb[(half + 2) * 128 + k] * w;
    }
    float bv = b2[j];
    {
        int r = half;
        if (row0 + r < rows) {
            float z = a0 + bv;
            outp[(size_t)(row0 + r) * OUTB + j] = 1.f / (1.f + __expf(-z));
        }
        r = half + 2;
        if (row0 + r < rows) {
            float z = a1 + bv;
            outp[(size_t)(row0 + r) * OUTB + j] = 1.f / (1.f + __expf(-z));
        }
    }
}

// ---------------- launch ----------------------------------------------------
extern "C" void kernel_launch(void* const* d_in, const int* in_sizes, int n_in,
                              void* d_out, int out_size) {
    const int*   row  = (const int*)  d_in[0];
    const int*   col  = (const int*)  d_in[1];
    const float* adj  = (const float*)d_in[2];
    const float* cond = (const float*)d_in[3];

    int nnz = in_sizes[0];
    int C   = in_sizes[3];
    int V   = out_size / OUTB;
    if (nnz > MAXNNZ) nnz = MAXNNZ;
    if (C > MAXC) C = MAXC;
    if (V > MAXV) V = MAXV;

    int w = 4;
    if (n_in >= 22 && in_sizes[4] == 1 && in_sizes[5] == 1) w = 6;
    const float* pc_w1 = (const float*)d_in[w + 0];
    const float* pc_b1 = (const float*)d_in[w + 1];
    const float* pc_w2 = (const float*)d_in[w + 2];
    const float* pc_b2 = (const float*)d_in[w + 3];
    const float* cu_w1 = (const float*)d_in[w + 4];
    const float* cu_b1 = (const float*)d_in[w + 5];
    const float* cu_w2 = (const float*)d_in[w + 6];
    const float* cu_b2 = (const float*)d_in[w + 7];
    const float* vu_w1 = (const float*)d_in[w + 8];
    const float* vu_b1 = (const float*)d_in[w + 9];
    const float* vu_w2 = (const float*)d_in[w + 10];
    const float* vu_b2 = (const float*)d_in[w + 11];
    const float* o_w1  = (const float*)d_in[w + 12];
    const float* o_b1  = (const float*)d_in[w + 13];
    const float* o_w2  = (const float*)d_in[w + 14];
    const float* o_b2  = (const float*)d_in[w + 15];

    float *p_vars, *p_cons, *p_v2c, *p_c2v;
    int   *p_offC, *p_offV, *p_cscRow, *p_csrCol;
    float *p_cscVal, *p_csrVal;
    cudaGetSymbolAddress((void**)&p_vars,   g_vars);
    cudaGetSymbolAddress((void**)&p_cons,   g_cons);
    cudaGetSymbolAddress((void**)&p_v2c,    g_v2c);
    cudaGetSymbolAddress((void**)&p_c2v,    g_c2v);
    cudaGetSymbolAddress((void**)&p_offC,   g_offC);
    cudaGetSymbolAddress((void**)&p_offV,   g_offV);
    cudaGetSymbolAddress((void**)&p_cscRow, g_cscRow);
    cudaGetSymbolAddress((void**)&p_cscVal, g_cscVal);
    cudaGetSymbolAddress((void**)&p_csrCol, g_csrCol);
    cudaGetSymbolAddress((void**)&p_csrVal, g_csrVal);

    int maxCV = (C > V) ? C : V;

    zero_counts_kernel<<<(maxCV + 255) / 256, 256>>>(C, V);
    hist_kernel<<<(nnz + 1023) / 1024, 256>>>(row, col, nnz);
    scan_kernel<<<2, 1024>>>(C, V);
    fill_kernel<<<(nnz + 1023) / 1024, 256>>>(row, col, adj, nnz);
    init_vars_kernel<<<(V * FM + 255) / 256, 256>>>(V * FM);
    prep_kernel<<<(C + 31) / 32, 256>>>(cond, pc_w1, pc_b1, pc_w2, pc_b2, C);

    for (int it = 0; it < 3; it++) {
        seg_gather_kernel<<<(C + 7) / 8, 256>>>(p_offC, p_cscRow, p_cscVal, p_vars, p_v2c, C);
        mlp128_kernel<<<(C + 31) / 32, 256>>>(p_cons, p_v2c, p_cons,
                                              cu_w1, cu_b1, cu_w2, cu_b2, C);
        seg_gather_kernel<<<(V + 7) / 8, 256>>>(p_offV, p_csrCol, p_csrVal, p_cons, p_c2v, V);
        mlp128_kernel<<<(V + 31) / 32, 256>>>(p_vars, p_c2v, p_vars,
                                              vu_w1, vu_b1, vu_w2, vu_b2, V);
    }

    out_kernel<<<(V + 31) / 32, 256>>>(o_w1, o_b1, o_w2, o_b2, (float*)d_out, V);
}

// round 6
// speedup vs baseline: 1.4192x; 1.4192x over previous
#include <cuda_runtime.h>
#include <cuda_bf16.h>
#include <cstdint>

#define FM        64
#define MAXV      100000
#define MAXC      50000
#define MAXNNZ    2000000
#define OUTB      16

typedef unsigned long long u64;
typedef unsigned int u32;

// ===================== scratch globals ======================================
__device__ float g_vars[MAXV * FM];
__device__ float g_cons[MAXC * FM];
__device__ float g_v2c [MAXC * FM];
__device__ float g_c2v [MAXV * FM];

__device__ int   g_cntC[MAXC];
__device__ int   g_cntV[MAXV];
__device__ int   g_offC[MAXC + 1];
__device__ int   g_offV[MAXV + 1];
__device__ int   g_curC[MAXC];
__device__ int   g_curV[MAXV];

__device__ int   g_cscRow[MAXNNZ];
__device__ float g_cscVal[MAXNNZ];
__device__ int   g_csrCol[MAXNNZ];
__device__ float g_csrVal[MAXNNZ];

// packed per-lane weight fragments (uint4 = {b0_hi, b1_hi, b0_lo, b1_lo})
// W1: [8 kchunk][16 ntile][32 lane] uint4 = 16384 u32
// W2: [8 kchunk][ 8 ntile][32 lane] uint4 =  8192 u32
__device__ u32 g_w1p_cu[16384];
__device__ u32 g_w2p_cu[8192];
__device__ u32 g_w1p_vu[16384];
__device__ u32 g_w2p_vu[8192];

// ===================== helpers ==============================================
__device__ __forceinline__ void bfsplit2(float f0, float f1, u32& hi, u32& lo) {
    __nv_bfloat162 h, l;
    h.x = __float2bfloat16(f0);
    h.y = __float2bfloat16(f1);
    l.x = __float2bfloat16(f0 - __bfloat162float(h.x));
    l.y = __float2bfloat16(f1 - __bfloat162float(h.y));
    hi = *(u32*)&h;
    lo = *(u32*)&l;
}

__device__ __forceinline__ void mma_bf16(float* d, u32 a0, u32 a1, u32 a2, u32 a3,
                                         u32 b0, u32 b1) {
    asm volatile(
        "mma.sync.aligned.m16n8k16.row.col.f32.bf16.bf16.f32 "
        "{%0,%1,%2,%3}, {%4,%5,%6,%7}, {%8,%9}, {%0,%1,%2,%3};"
        : "+f"(d[0]), "+f"(d[1]), "+f"(d[2]), "+f"(d[3])
        : "r"(a0), "r"(a1), "r"(a2), "r"(a3), "r"(b0), "r"(b1));
}

// ===================== CSR/CSC build ========================================
__global__ void zero_counts_kernel(int nC, int nV) {
    int i = blockIdx.x * blockDim.x + threadIdx.x;
    if (i < nC) g_cntC[i] = 0;
    if (i < nV) g_cntV[i] = 0;
}

__global__ void hist_kernel(const int* __restrict__ row, const int* __restrict__ col, int nnz) {
    int base = blockIdx.x * blockDim.x * 4 + threadIdx.x;
#pragma unroll
    for (int j = 0; j < 4; j++) {
        int e = base + j * blockDim.x;
        if (e < nnz) {
            atomicAdd(&g_cntC[col[e]], 1);
            atomicAdd(&g_cntV[row[e]], 1);
        }
    }
}

__global__ void scan_kernel(int nC, int nV) {
    const int* cnt; int* off; int* cur; int n;
    if (blockIdx.x == 0) { cnt = g_cntC; off = g_offC; cur = g_curC; n = nC; }
    else                 { cnt = g_cntV; off = g_offV; cur = g_curV; n = nV; }

    __shared__ int part[1024];
    int t = threadIdx.x;
    int chunk = (n + 1023) / 1024;
    int beg = t * chunk;
    int end = min(n, beg + chunk);

    int s = 0;
    for (int i = beg; i < end; i++) s += cnt[i];
    part[t] = s;
    __syncthreads();
    for (int d = 1; d < 1024; d <<= 1) {
        int v = (t >= d) ? part[t - d] : 0;
        __syncthreads();
        part[t] += v;
        __syncthreads();
    }
    int run = (t == 0) ? 0 : part[t - 1];
    for (int i = beg; i < end; i++) {
        off[i] = run; cur[i] = run;
        run += cnt[i];
    }
    if (t == 1023) off[n] = part[1023];
}

__global__ void fill_kernel(const int* __restrict__ row, const int* __restrict__ col,
                            const float* __restrict__ av, int nnz) {
    int base = blockIdx.x * blockDim.x * 4 + threadIdx.x;
#pragma unroll
    for (int j = 0; j < 4; j++) {
        int e = base + j * blockDim.x;
        if (e < nnz) {
            int r = row[e], c = col[e];
            float v = fabsf(av[e]);
            int p = atomicAdd(&g_curC[c], 1);
            g_cscRow[p] = r; g_cscVal[p] = v;
            int q = atomicAdd(&g_curV[r], 1);
            g_csrCol[q] = c; g_csrVal[q] = v;
        }
    }
}

__global__ void init_vars_kernel(int n) {
    int i = blockIdx.x * blockDim.x + threadIdx.x;
    if (i < n) g_vars[i] = 1.0f;
}

// ===================== weight fragment packing ==============================
// b0 of ntile j, kchunk t, lane l covers W[k][n], W[k+1][n] with
//   k = 16t + 2*(l&3) (+8 for b1), n = 8j + (l>>2)
__global__ void conv_w_kernel(const float* __restrict__ W1, const float* __restrict__ W2,
                              u32* __restrict__ w1p, u32* __restrict__ w2p) {
    int idx = blockIdx.x * blockDim.x + threadIdx.x;   // 16384 threads
    {
        int pos  = idx & 3;
        int lane = (idx >> 2) & 31;
        int j    = (idx >> 7) & 15;
        int t    = idx >> 11;
        int k = t * 16 + 2 * (lane & 3) + ((pos & 1) ? 8 : 0);
        int n = j * 8 + (lane >> 2);
        float f0 = W1[k * 128 + n];
        float f1 = W1[(k + 1) * 128 + n];
        u32 hi, lo;
        bfsplit2(f0, f1, hi, lo);
        w1p[idx] = (pos >= 2) ? lo : hi;
    }
    if (idx < 8192) {
        int pos  = idx & 3;
        int lane = (idx >> 2) & 31;
        int j    = (idx >> 7) & 7;
        int t    = idx >> 10;
        int k = t * 16 + 2 * (lane & 3) + ((pos & 1) ? 8 : 0);
        int n = j * 8 + (lane >> 2);
        float f0 = W2[k * 64 + n];
        float f1 = W2[(k + 1) * 64 + n];
        u32 hi, lo;
        bfsplit2(f0, f1, hi, lo);
        w2p[idx] = (pos >= 2) ? lo : hi;
    }
}

// ===================== segment gather-reduce (warp per segment) ============
__global__ void seg_gather_kernel(const int* __restrict__ offs,
                                  const int* __restrict__ idxArr,
                                  const float* __restrict__ valArr,
                                  const float* __restrict__ srcF,
                                  float* __restrict__ dstF, int nseg) {
    int warp = threadIdx.x >> 5;
    int lane = threadIdx.x & 31;
    int seg  = blockIdx.x * (blockDim.x >> 5) + warp;
    if (seg >= nseg) return;

    int s = offs[seg], e = offs[seg + 1];
    float ax = 0.f, ay = 0.f;
    int p = s;
    for (; p + 4 <= e; p += 4) {
        int   i0 = idxArr[p + 0], i1 = idxArr[p + 1], i2 = idxArr[p + 2], i3 = idxArr[p + 3];
        float v0 = valArr[p + 0], v1 = valArr[p + 1], v2 = valArr[p + 2], v3 = valArr[p + 3];
        float2 f0 = *(const float2*)&srcF[(size_t)i0 * FM + 2 * lane];
        float2 f1 = *(const float2*)&srcF[(size_t)i1 * FM + 2 * lane];
        float2 f2 = *(const float2*)&srcF[(size_t)i2 * FM + 2 * lane];
        float2 f3 = *(const float2*)&srcF[(size_t)i3 * FM + 2 * lane];
        ax += v0 * f0.x; ay += v0 * f0.y;
        ax += v1 * f1.x; ay += v1 * f1.y;
        ax += v2 * f2.x; ay += v2 * f2.y;
        ax += v3 * f3.x; ay += v3 * f3.y;
    }
    for (; p < e; p++) {
        int   i0 = idxArr[p];
        float v0 = valArr[p];
        float2 f0 = *(const float2*)&srcF[(size_t)i0 * FM + 2 * lane];
        ax += v0 * f0.x; ay += v0 * f0.y;
    }
    *(float2*)&dstF[(size_t)seg * FM + 2 * lane] = make_float2(ax, ay);
}

// ===================== MMA MLP: concat(inA,inB)->128(relu)->64 ==============
// CTA = 256 threads = 8 warps; warp handles 16 rows; layer1 D chains into
// layer2 A fragments in registers (m16n8 C layout == m16k16 A layout halves).
__global__ void __launch_bounds__(256) mlp_mma_kernel(
        const float* __restrict__ inA, const float* __restrict__ inB,
        float* __restrict__ outp,
        const uint4* __restrict__ w1p, const float* __restrict__ b1,
        const uint4* __restrict__ w2p, const float* __restrict__ b2,
        int rows) {
    int tid = threadIdx.x;
    int wid = tid >> 5;
    int lane = tid & 31;
    int m = lane & 3;          // col-pair index within quad
    int g = lane >> 2;         // row within 8-row group

    int rbase = blockIdx.x * 128 + wid * 16;
    if (rbase >= rows) return;
    int r0 = rbase + g, r1 = rbase + g + 8;
    int rr0 = min(r0, rows - 1), rr1 = min(r1, rows - 1);

    // ---- layer 1: D1[16 rows, 128 cols] over K=128 -------------------------
    float d1[16][4];
#pragma unroll
    for (int j = 0; j < 16; j++)
#pragma unroll
        for (int q = 0; q < 4; q++) d1[j][q] = 0.f;

#pragma unroll
    for (int t = 0; t < 8; t++) {
        const float* src = (t < 4) ? inA : inB;
        int kc = (t & 3) * 16 + 2 * m;
        float2 x0 = *(const float2*)&src[(size_t)rr0 * 64 + kc];
        float2 x1 = *(const float2*)&src[(size_t)rr1 * 64 + kc];
        float2 x2 = *(const float2*)&src[(size_t)rr0 * 64 + kc + 8];
        float2 x3 = *(const float2*)&src[(size_t)rr1 * 64 + kc + 8];
        u32 ah0, al0, ah1, al1, ah2, al2, ah3, al3;
        bfsplit2(x0.x, x0.y, ah0, al0);
        bfsplit2(x1.x, x1.y, ah1, al1);
        bfsplit2(x2.x, x2.y, ah2, al2);
        bfsplit2(x3.x, x3.y, ah3, al3);

        const uint4* wp = w1p + (size_t)(t * 16) * 32 + lane;
#pragma unroll
        for (int j = 0; j < 16; j++) {
            uint4 w = __ldg(&wp[j * 32]);
            mma_bf16(d1[j], ah0, ah1, ah2, ah3, w.x, w.y);   // hi*hi
            mma_bf16(d1[j], ah0, ah1, ah2, ah3, w.z, w.w);   // hi*lo
            mma_bf16(d1[j], al0, al1, al2, al3, w.x, w.y);   // lo*hi
        }
    }

    // ---- layer 2: bias+relu+split in registers, D2[16 rows, 64 cols] -------
    float d2[8][4];
#pragma unroll
    for (int j = 0; j < 8; j++)
#pragma unroll
        for (int q = 0; q < 4; q++) d2[j][q] = 0.f;

#pragma unroll
    for (int t = 0; t < 8; t++) {
        // layer2 kchunk t = layer1 cols 16t..16t+15 = ntiles 2t, 2t+1
        float2 ba = *(const float2*)&b1[16 * t + 2 * m];
        float2 bb = *(const float2*)&b1[16 * t + 8 + 2 * m];
        float f0 = fmaxf(d1[2 * t][0] + ba.x, 0.f);
        float f1 = fmaxf(d1[2 * t][1] + ba.y, 0.f);
        float f2 = fmaxf(d1[2 * t][2] + ba.x, 0.f);
        float f3 = fmaxf(d1[2 * t][3] + ba.y, 0.f);
        float f4 = fmaxf(d1[2 * t + 1][0] + bb.x, 0.f);
        float f5 = fmaxf(d1[2 * t + 1][1] + bb.y, 0.f);
        float f6 = fmaxf(d1[2 * t + 1][2] + bb.x, 0.f);
        float f7 = fmaxf(d1[2 * t + 1][3] + bb.y, 0.f);
        u32 ah0, al0, ah1, al1, ah2, al2, ah3, al3;
        bfsplit2(f0, f1, ah0, al0);   // a0: row g,   k = 16t+2m..
        bfsplit2(f2, f3, ah1, al1);   // a1: row g+8
        bfsplit2(f4, f5, ah2, al2);   // a2: row g,   k+8
        bfsplit2(f6, f7, ah3, al3);   // a3: row g+8, k+8

        const uint4* wp = w2p + (size_t)(t * 8) * 32 + lane;
#pragma unroll
        for (int j = 0; j < 8; j++) {
            uint4 w = __ldg(&wp[j * 32]);
            mma_bf16(d2[j], ah0, ah1, ah2, ah3, w.x, w.y);
            mma_bf16(d2[j], ah0, ah1, ah2, ah3, w.z, w.w);
            mma_bf16(d2[j], al0, al1, al2, al3, w.x, w.y);
        }
    }

    // ---- store: bias + fp32 out --------------------------------------------
#pragma unroll
    for (int j = 0; j < 8; j++) {
        float2 b = *(const float2*)&b2[8 * j + 2 * m];
        if (r0 < rows) {
            *(float2*)&outp[(size_t)r0 * 64 + 8 * j + 2 * m] =
                make_float2(d2[j][0] + b.x, d2[j][1] + b.y);
        }
        if (r1 < rows) {
            *(float2*)&outp[(size_t)r1 * 64 + 8 * j + 2 * m] =
                make_float2(d2[j][2] + b.x, d2[j][3] + b.y);
        }
    }
}

// ===================== scalar prep / out kernels ============================
__device__ __forceinline__ void mlp_layer2_64(const float* sbuf,
                                              const float* __restrict__ W2,
                                              const float* __restrict__ b2,
                                              float* __restrict__ outp,
                                              int row0, int rows, int lane) {
    float2 acc[4];
#pragma unroll
    for (int r = 0; r < 4; r++) acc[r] = make_float2(0.f, 0.f);

    for (int k = 0; k < 128; k += 4) {
        float4 hv[4];
#pragma unroll
        for (int r = 0; r < 4; r++) hv[r] = *(const float4*)&sbuf[r * 128 + k];
#pragma unroll
        for (int kk = 0; kk < 4; kk++) {
            float2 w = *(const float2*)&W2[(k + kk) * 64 + 2 * lane];
#pragma unroll
            for (int r = 0; r < 4; r++) {
                float hk = ((const float*)&hv[r])[kk];
                acc[r].x += hk * w.x;
                acc[r].y += hk * w.y;
            }
        }
    }
    float2 bb = *(const float2*)&b2[2 * lane];
#pragma unroll
    for (int r = 0; r < 4; r++) {
        if (row0 + r < rows) {
            *(float2*)&outp[(size_t)(row0 + r) * 64 + 2 * lane] =
                make_float2(acc[r].x + bb.x, acc[r].y + bb.y);
        }
    }
}

__global__ void __launch_bounds__(256) prep_kernel(
                            const float* __restrict__ cond,
                            const float* __restrict__ w1, const float* __restrict__ b1,
                            const float* __restrict__ w2, const float* __restrict__ b2,
                            int rows) {
    __shared__ float sbuf[8][512];
    int warp = threadIdx.x >> 5;
    int lane = threadIdx.x & 31;
    int row0 = (blockIdx.x * 8 + warp) * 4;
    if (row0 >= rows) return;
    float* sbf = sbuf[warp];

    float4 w = *(const float4*)&w1[4 * lane];
    float4 b = *(const float4*)&b1[4 * lane];
#pragma unroll
    for (int r = 0; r < 4; r++) {
        int row = min(row0 + r, rows - 1);
        float c = cond[row];
        float4 h;
        h.x = fmaxf(c * w.x + b.x, 0.f);
        h.y = fmaxf(c * w.y + b.y, 0.f);
        h.z = fmaxf(c * w.z + b.z, 0.f);
        h.w = fmaxf(c * w.w + b.w, 0.f);
        *(float4*)&sbf[r * 128 + 4 * lane] = h;
    }
    __syncwarp();
    mlp_layer2_64(sbf, w2, b2, g_cons, row0, rows, lane);
}

__global__ void __launch_bounds__(256) out_kernel(
                           const float* __restrict__ W1, const float* __restrict__ b1,
                           const float* __restrict__ W2, const float* __restrict__ b2,
                           float* __restrict__ outp, int rows) {
    __shared__ float sbuf[8][512];
    int warp = threadIdx.x >> 5;
    int lane = threadIdx.x & 31;
    int row0 = (blockIdx.x * 8 + warp) * 4;
    if (row0 >= rows) return;
    float* sbf = sbuf[warp];

#pragma unroll
    for (int r = 0; r < 4; r++) {
        int row = min(row0 + r, rows - 1);
        float2 v = *(const float2*)&g_vars[(size_t)row * 64 + 2 * lane];
        *(float2*)&sbf[r * 128 + 2 * lane] = v;
    }
    __syncwarp();

    float4 acc[4];
#pragma unroll
    for (int r = 0; r < 4; r++) acc[r] = make_float4(0.f, 0.f, 0.f, 0.f);
    for (int k = 0; k < 64; k += 4) {
        float4 xv[4];
#pragma unroll
        for (int r = 0; r < 4; r++) xv[r] = *(const float4*)&sbf[r * 128 + k];
#pragma unroll
        for (int kk = 0; kk < 4; kk++) {
            float4 w = *(const float4*)&W1[(k + kk) * 128 + 4 * lane];
#pragma unroll
            for (int r = 0; r < 4; r++) {
                float xk = ((const float*)&xv[r])[kk];
                acc[r].x += xk * w.x;
                acc[r].y += xk * w.y;
                acc[r].z += xk * w.z;
                acc[r].w += xk * w.w;
            }
        }
    }
    float4 bb = *(const float4*)&b1[4 * lane];
    __syncwarp();
#pragma unroll
    for (int r = 0; r < 4; r++) {
        float4 h;
        h.x = fmaxf(acc[r].x + bb.x, 0.f);
        h.y = fmaxf(acc[r].y + bb.y, 0.f);
        h.z = fmaxf(acc[r].z + bb.z, 0.f);
        h.w = fmaxf(acc[r].w + bb.w, 0.f);
        *(float4*)&sbf[r * 128 + 4 * lane] = h;
    }
    __syncwarp();

    int j = lane & 15;
    int half = lane >> 4;
    float a0 = 0.f, a1 = 0.f;
#pragma unroll 4
    for (int k = 0; k < 128; k++) {
        float w = W2[k * 16 + j];
        a0 += sbf[half * 128 + k] * w;
        a1 += sbf[(half + 2) * 128 + k] * w;
    }
    float bv = b2[j];
    {
        int r = half;
        if (row0 + r < rows) {
            float z = a0 + bv;
            outp[(size_t)(row0 + r) * OUTB + j] = 1.f / (1.f + __expf(-z));
        }
        r = half + 2;
        if (row0 + r < rows) {
            float z = a1 + bv;
            outp[(size_t)(row0 + r) * OUTB + j] = 1.f / (1.f + __expf(-z));
        }
    }
}

// ===================== launch ===============================================
extern "C" void kernel_launch(void* const* d_in, const int* in_sizes, int n_in,
                              void* d_out, int out_size) {
    const int*   row  = (const int*)  d_in[0];
    const int*   col  = (const int*)  d_in[1];
    const float* adj  = (const float*)d_in[2];
    const float* cond = (const float*)d_in[3];

    int nnz = in_sizes[0];
    int C   = in_sizes[3];
    int V   = out_size / OUTB;
    if (nnz > MAXNNZ) nnz = MAXNNZ;
    if (C > MAXC) C = MAXC;
    if (V > MAXV) V = MAXV;

    int w = 4;
    if (n_in >= 22 && in_sizes[4] == 1 && in_sizes[5] == 1) w = 6;
    const float* pc_w1 = (const float*)d_in[w + 0];
    const float* pc_b1 = (const float*)d_in[w + 1];
    const float* pc_w2 = (const float*)d_in[w + 2];
    const float* pc_b2 = (const float*)d_in[w + 3];
    const float* cu_w1 = (const float*)d_in[w + 4];
    const float* cu_b1 = (const float*)d_in[w + 5];
    const float* cu_w2 = (const float*)d_in[w + 6];
    const float* cu_b2 = (const float*)d_in[w + 7];
    const float* vu_w1 = (const float*)d_in[w + 8];
    const float* vu_b1 = (const float*)d_in[w + 9];
    const float* vu_w2 = (const float*)d_in[w + 10];
    const float* vu_b2 = (const float*)d_in[w + 11];
    const float* o_w1  = (const float*)d_in[w + 12];
    const float* o_b1  = (const float*)d_in[w + 13];
    const float* o_w2  = (const float*)d_in[w + 14];
    const float* o_b2  = (const float*)d_in[w + 15];

    float *p_vars, *p_cons, *p_v2c, *p_c2v;
    int   *p_offC, *p_offV, *p_cscRow, *p_csrCol;
    float *p_cscVal, *p_csrVal;
    u32   *p_w1cu, *p_w2cu, *p_w1vu, *p_w2vu;
    cudaGetSymbolAddress((void**)&p_vars,   g_vars);
    cudaGetSymbolAddress((void**)&p_cons,   g_cons);
    cudaGetSymbolAddress((void**)&p_v2c,    g_v2c);
    cudaGetSymbolAddress((void**)&p_c2v,    g_c2v);
    cudaGetSymbolAddress((void**)&p_offC,   g_offC);
    cudaGetSymbolAddress((void**)&p_offV,   g_offV);
    cudaGetSymbolAddress((void**)&p_cscRow, g_cscRow);
    cudaGetSymbolAddress((void**)&p_cscVal, g_cscVal);
    cudaGetSymbolAddress((void**)&p_csrCol, g_csrCol);
    cudaGetSymbolAddress((void**)&p_csrVal, g_csrVal);
    cudaGetSymbolAddress((void**)&p_w1cu,   g_w1p_cu);
    cudaGetSymbolAddress((void**)&p_w2cu,   g_w2p_cu);
    cudaGetSymbolAddress((void**)&p_w1vu,   g_w1p_vu);
    cudaGetSymbolAddress((void**)&p_w2vu,   g_w2p_vu);

    int maxCV = (C > V) ? C : V;

    zero_counts_kernel<<<(maxCV + 255) / 256, 256>>>(C, V);
    hist_kernel<<<(nnz + 1023) / 1024, 256>>>(row, col, nnz);
    scan_kernel<<<2, 1024>>>(C, V);
    fill_kernel<<<(nnz + 1023) / 1024, 256>>>(row, col, adj, nnz);
    init_vars_kernel<<<(V * FM + 255) / 256, 256>>>(V * FM);
    conv_w_kernel<<<64, 256>>>(cu_w1, cu_w2, p_w1cu, p_w2cu);
    conv_w_kernel<<<64, 256>>>(vu_w1, vu_w2, p_w1vu, p_w2vu);
    prep_kernel<<<(C + 31) / 32, 256>>>(cond, pc_w1, pc_b1, pc_w2, pc_b2, C);

    int gC = (C + 127) / 128;
    int gV = (V + 127) / 128;
    for (int it = 0; it < 3; it++) {
        seg_gather_kernel<<<(C + 7) / 8, 256>>>(p_offC, p_cscRow, p_cscVal, p_vars, p_v2c, C);
        mlp_mma_kernel<<<gC, 256>>>(p_cons, p_v2c, p_cons,
                                    (const uint4*)p_w1cu, cu_b1, (const uint4*)p_w2cu, cu_b2, C);
        seg_gather_kernel<<<(V + 7) / 8, 256>>>(p_offV, p_csrCol, p_csrVal, p_cons, p_c2v, V);
        mlp_mma_kernel<<<gV, 256>>>(p_vars, p_c2v, p_vars,
                                    (const uint4*)p_w1vu, vu_b1, (const uint4*)p_w2vu, vu_b2, V);
    }

    out_kernel<<<(V + 31) / 32, 256>>>(o_w1, o_b1, o_w2, o_b2, (float*)d_out, V);
}

// round 7
// speedup vs baseline: 1.4853x; 1.0466x over previous
#include <cuda_runtime.h>
#include <cuda_bf16.h>
#include <cstdint>

#define FM        64
#define MAXV      100000
#define MAXC      50000
#define MAXNNZ    2000000
#define OUTB      16

typedef unsigned long long u64;
typedef unsigned int u32;

// ===================== scratch globals ======================================
__device__ float g_vars[MAXV * FM];
__device__ float g_cons[MAXC * FM];
__device__ float g_v2c [MAXC * FM];
__device__ float g_c2v [MAXV * FM];

__device__ int   g_cntC[MAXC];
__device__ int   g_cntV[MAXV];
__device__ int   g_offC[MAXC + 1];
__device__ int   g_offV[MAXV + 1];
__device__ int   g_curC[MAXC];
__device__ int   g_curV[MAXV];

// packed edge entries: low 32 = index, high 32 = fp32 bits of |val|
__device__ u64   g_cscE[MAXNNZ];
__device__ u64   g_csrE[MAXNNZ];

// packed per-lane weight fragments (uint4 = {b0_hi, b1_hi, b0_lo, b1_lo})
__device__ u32 g_w1p_cu[16384];
__device__ u32 g_w2p_cu[8192];
__device__ u32 g_w1p_vu[16384];
__device__ u32 g_w2p_vu[8192];
__device__ u32 g_w1p_out[8192];    // out W1: [4 kchunk][16 ntile][32 lane] uint4
__device__ u32 g_w2p_out[2048];    // out W2: [8 kchunk][ 2 ntile][32 lane] uint4

// ===================== helpers ==============================================
__device__ __forceinline__ void bfsplit2(float f0, float f1, u32& hi, u32& lo) {
    __nv_bfloat162 h, l;
    h.x = __float2bfloat16(f0);
    h.y = __float2bfloat16(f1);
    l.x = __float2bfloat16(f0 - __bfloat162float(h.x));
    l.y = __float2bfloat16(f1 - __bfloat162float(h.y));
    hi = *(u32*)&h;
    lo = *(u32*)&l;
}

__device__ __forceinline__ void mma_bf16(float* d, u32 a0, u32 a1, u32 a2, u32 a3,
                                         u32 b0, u32 b1) {
    asm volatile(
        "mma.sync.aligned.m16n8k16.row.col.f32.bf16.bf16.f32 "
        "{%0,%1,%2,%3}, {%4,%5,%6,%7}, {%8,%9}, {%0,%1,%2,%3};"
        : "+f"(d[0]), "+f"(d[1]), "+f"(d[2]), "+f"(d[3])
        : "r"(a0), "r"(a1), "r"(a2), "r"(a3), "r"(b0), "r"(b1));
}

// ===================== CSR/CSC build ========================================
__global__ void zero_counts_kernel(int nC, int nV) {
    int i = blockIdx.x * blockDim.x + threadIdx.x;
    if (i < nC) g_cntC[i] = 0;
    if (i < nV) g_cntV[i] = 0;
}

__global__ void hist_kernel(const int* __restrict__ row, const int* __restrict__ col, int nnz) {
    int base = blockIdx.x * blockDim.x * 8 + threadIdx.x;
#pragma unroll
    for (int j = 0; j < 8; j++) {
        int e = base + j * blockDim.x;
        if (e < nnz) {
            atomicAdd(&g_cntC[col[e]], 1);
            atomicAdd(&g_cntV[row[e]], 1);
        }
    }
}

__global__ void scan_kernel(int nC, int nV) {
    const int* cnt; int* off; int* cur; int n;
    if (blockIdx.x == 0) { cnt = g_cntC; off = g_offC; cur = g_curC; n = nC; }
    else                 { cnt = g_cntV; off = g_offV; cur = g_curV; n = nV; }

    __shared__ int part[1024];
    int t = threadIdx.x;
    int chunk = (n + 1023) / 1024;
    int beg = t * chunk;
    int end = min(n, beg + chunk);

    int s = 0;
    for (int i = beg; i < end; i++) s += cnt[i];
    part[t] = s;
    __syncthreads();
    for (int d = 1; d < 1024; d <<= 1) {
        int v = (t >= d) ? part[t - d] : 0;
        __syncthreads();
        part[t] += v;
        __syncthreads();
    }
    int run = (t == 0) ? 0 : part[t - 1];
    for (int i = beg; i < end; i++) {
        off[i] = run; cur[i] = run;
        run += cnt[i];
    }
    if (t == 1023) off[n] = part[1023];
}

__global__ void fill_kernel(const int* __restrict__ row, const int* __restrict__ col,
                            const float* __restrict__ av, int nnz) {
    int base = blockIdx.x * blockDim.x * 4 + threadIdx.x;
    int e[4], r[4], c[4];
    u32 vb[4];
    bool ok[4];
#pragma unroll
    for (int j = 0; j < 4; j++) {
        e[j] = base + j * blockDim.x;
        ok[j] = e[j] < nnz;
        if (ok[j]) {
            r[j] = row[e[j]];
            c[j] = col[e[j]];
            vb[j] = __float_as_uint(fabsf(av[e[j]]));
        }
    }
    int p[4], q[4];
#pragma unroll
    for (int j = 0; j < 4; j++) {
        if (ok[j]) {
            p[j] = atomicAdd(&g_curC[c[j]], 1);
            q[j] = atomicAdd(&g_curV[r[j]], 1);
        }
    }
#pragma unroll
    for (int j = 0; j < 4; j++) {
        if (ok[j]) {
            g_cscE[p[j]] = ((u64)vb[j] << 32) | (u32)r[j];
            g_csrE[q[j]] = ((u64)vb[j] << 32) | (u32)c[j];
        }
    }
}

__global__ void init_vars_kernel(int n) {
    int i = blockIdx.x * blockDim.x + threadIdx.x;
    if (i < n) g_vars[i] = 1.0f;
}

// ===================== weight fragment packing ==============================
__global__ void conv_w_kernel(const float* __restrict__ W1, const float* __restrict__ W2,
                              u32* __restrict__ w1p, u32* __restrict__ w2p) {
    int idx = blockIdx.x * blockDim.x + threadIdx.x;   // 16384 threads
    {
        int pos  = idx & 3;
        int lane = (idx >> 2) & 31;
        int j    = (idx >> 7) & 15;
        int t    = idx >> 11;
        int k = t * 16 + 2 * (lane & 3) + ((pos & 1) ? 8 : 0);
        int n = j * 8 + (lane >> 2);
        float f0 = W1[k * 128 + n];
        float f1 = W1[(k + 1) * 128 + n];
        u32 hi, lo;
        bfsplit2(f0, f1, hi, lo);
        w1p[idx] = (pos >= 2) ? lo : hi;
    }
    if (idx < 8192) {
        int pos  = idx & 3;
        int lane = (idx >> 2) & 31;
        int j    = (idx >> 7) & 7;
        int t    = idx >> 10;
        int k = t * 16 + 2 * (lane & 3) + ((pos & 1) ? 8 : 0);
        int n = j * 8 + (lane >> 2);
        float f0 = W2[k * 64 + n];
        float f1 = W2[(k + 1) * 64 + n];
        u32 hi, lo;
        bfsplit2(f0, f1, hi, lo);
        w2p[idx] = (pos >= 2) ? lo : hi;
    }
}

// out MLP: W1 [64][128], W2 [128][16]
__global__ void conv_w_out_kernel(const float* __restrict__ W1, const float* __restrict__ W2,
                                  u32* __restrict__ w1p, u32* __restrict__ w2p) {
    int idx = blockIdx.x * blockDim.x + threadIdx.x;   // 8192 threads
    {
        int pos  = idx & 3;
        int lane = (idx >> 2) & 31;
        int j    = (idx >> 7) & 15;
        int t    = idx >> 11;            // 0..3
        int k = t * 16 + 2 * (lane & 3) + ((pos & 1) ? 8 : 0);
        int n = j * 8 + (lane >> 2);
        float f0 = W1[k * 128 + n];
        float f1 = W1[(k + 1) * 128 + n];
        u32 hi, lo;
        bfsplit2(f0, f1, hi, lo);
        w1p[idx] = (pos >= 2) ? lo : hi;
    }
    if (idx < 2048) {
        int pos  = idx & 3;
        int lane = (idx >> 2) & 31;
        int j    = (idx >> 7) & 1;
        int t    = idx >> 8;             // 0..7
        int k = t * 16 + 2 * (lane & 3) + ((pos & 1) ? 8 : 0);
        int n = j * 8 + (lane >> 2);
        float f0 = W2[k * 16 + n];
        float f1 = W2[(k + 1) * 16 + n];
        u32 hi, lo;
        bfsplit2(f0, f1, hi, lo);
        w2p[idx] = (pos >= 2) ? lo : hi;
    }
}

// ===================== segment gather-reduce (warp per segment) ============
__global__ void seg_gather_kernel(const int* __restrict__ offs,
                                  const u64* __restrict__ edges,
                                  const float* __restrict__ srcF,
                                  float* __restrict__ dstF, int nseg) {
    int warp = threadIdx.x >> 5;
    int lane = threadIdx.x & 31;
    int seg  = blockIdx.x * (blockDim.x >> 5) + warp;
    if (seg >= nseg) return;

    int s = offs[seg], e = offs[seg + 1];
    float ax = 0.f, ay = 0.f;
    int p = s;
    for (; p + 4 <= e; p += 4) {
        u64 e0 = __ldg(&edges[p + 0]);
        u64 e1 = __ldg(&edges[p + 1]);
        u64 e2 = __ldg(&edges[p + 2]);
        u64 e3 = __ldg(&edges[p + 3]);
        float2 f0 = *(const float2*)&srcF[(size_t)(u32)e0 * FM + 2 * lane];
        float2 f1 = *(const float2*)&srcF[(size_t)(u32)e1 * FM + 2 * lane];
        float2 f2 = *(const float2*)&srcF[(size_t)(u32)e2 * FM + 2 * lane];
        float2 f3 = *(const float2*)&srcF[(size_t)(u32)e3 * FM + 2 * lane];
        float v0 = __uint_as_float((u32)(e0 >> 32));
        float v1 = __uint_as_float((u32)(e1 >> 32));
        float v2 = __uint_as_float((u32)(e2 >> 32));
        float v3 = __uint_as_float((u32)(e3 >> 32));
        ax += v0 * f0.x; ay += v0 * f0.y;
        ax += v1 * f1.x; ay += v1 * f1.y;
        ax += v2 * f2.x; ay += v2 * f2.y;
        ax += v3 * f3.x; ay += v3 * f3.y;
    }
    for (; p < e; p++) {
        u64 e0 = __ldg(&edges[p]);
        float2 f0 = *(const float2*)&srcF[(size_t)(u32)e0 * FM + 2 * lane];
        float v0 = __uint_as_float((u32)(e0 >> 32));
        ax += v0 * f0.x; ay += v0 * f0.y;
    }
    *(float2*)&dstF[(size_t)seg * FM + 2 * lane] = make_float2(ax, ay);
}

// ===================== MMA MLP: concat(inA,inB)->128(relu)->64 ==============
__global__ void __launch_bounds__(256) mlp_mma_kernel(
        const float* __restrict__ inA, const float* __restrict__ inB,
        float* __restrict__ outp,
        const uint4* __restrict__ w1p, const float* __restrict__ b1,
        const uint4* __restrict__ w2p, const float* __restrict__ b2,
        int rows) {
    int tid = threadIdx.x;
    int wid = tid >> 5;
    int lane = tid & 31;
    int m = lane & 3;
    int g = lane >> 2;

    int rbase = blockIdx.x * 128 + wid * 16;
    if (rbase >= rows) return;
    int r0 = rbase + g, r1 = rbase + g + 8;
    int rr0 = min(r0, rows - 1), rr1 = min(r1, rows - 1);

    float d1[16][4];
#pragma unroll
    for (int j = 0; j < 16; j++)
#pragma unroll
        for (int q = 0; q < 4; q++) d1[j][q] = 0.f;

#pragma unroll
    for (int t = 0; t < 8; t++) {
        const float* src = (t < 4) ? inA : inB;
        int kc = (t & 3) * 16 + 2 * m;
        float2 x0 = *(const float2*)&src[(size_t)rr0 * 64 + kc];
        float2 x1 = *(const float2*)&src[(size_t)rr1 * 64 + kc];
        float2 x2 = *(const float2*)&src[(size_t)rr0 * 64 + kc + 8];
        float2 x3 = *(const float2*)&src[(size_t)rr1 * 64 + kc + 8];
        u32 ah0, al0, ah1, al1, ah2, al2, ah3, al3;
        bfsplit2(x0.x, x0.y, ah0, al0);
        bfsplit2(x1.x, x1.y, ah1, al1);
        bfsplit2(x2.x, x2.y, ah2, al2);
        bfsplit2(x3.x, x3.y, ah3, al3);

        const uint4* wp = w1p + (size_t)(t * 16) * 32 + lane;
#pragma unroll
        for (int j = 0; j < 16; j++) {
            uint4 w = __ldg(&wp[j * 32]);
            mma_bf16(d1[j], ah0, ah1, ah2, ah3, w.x, w.y);
            mma_bf16(d1[j], ah0, ah1, ah2, ah3, w.z, w.w);
            mma_bf16(d1[j], al0, al1, al2, al3, w.x, w.y);
        }
    }

    float d2[8][4];
#pragma unroll
    for (int j = 0; j < 8; j++)
#pragma unroll
        for (int q = 0; q < 4; q++) d2[j][q] = 0.f;

#pragma unroll
    for (int t = 0; t < 8; t++) {
        float2 ba = *(const float2*)&b1[16 * t + 2 * m];
        float2 bb = *(const float2*)&b1[16 * t + 8 + 2 * m];
        float f0 = fmaxf(d1[2 * t][0] + ba.x, 0.f);
        float f1 = fmaxf(d1[2 * t][1] + ba.y, 0.f);
        float f2 = fmaxf(d1[2 * t][2] + ba.x, 0.f);
        float f3 = fmaxf(d1[2 * t][3] + ba.y, 0.f);
        float f4 = fmaxf(d1[2 * t + 1][0] + bb.x, 0.f);
        float f5 = fmaxf(d1[2 * t + 1][1] + bb.y, 0.f);
        float f6 = fmaxf(d1[2 * t + 1][2] + bb.x, 0.f);
        float f7 = fmaxf(d1[2 * t + 1][3] + bb.y, 0.f);
        u32 ah0, al0, ah1, al1, ah2, al2, ah3, al3;
        bfsplit2(f0, f1, ah0, al0);
        bfsplit2(f2, f3, ah1, al1);
        bfsplit2(f4, f5, ah2, al2);
        bfsplit2(f6, f7, ah3, al3);

        const uint4* wp = w2p + (size_t)(t * 8) * 32 + lane;
#pragma unroll
        for (int j = 0; j < 8; j++) {
            uint4 w = __ldg(&wp[j * 32]);
            mma_bf16(d2[j], ah0, ah1, ah2, ah3, w.x, w.y);
            mma_bf16(d2[j], ah0, ah1, ah2, ah3, w.z, w.w);
            mma_bf16(d2[j], al0, al1, al2, al3, w.x, w.y);
        }
    }

#pragma unroll
    for (int j = 0; j < 8; j++) {
        float2 b = *(const float2*)&b2[8 * j + 2 * m];
        if (r0 < rows) {
            *(float2*)&outp[(size_t)r0 * 64 + 8 * j + 2 * m] =
                make_float2(d2[j][0] + b.x, d2[j][1] + b.y);
        }
        if (r1 < rows) {
            *(float2*)&outp[(size_t)r1 * 64 + 8 * j + 2 * m] =
                make_float2(d2[j][2] + b.x, d2[j][3] + b.y);
        }
    }
}

// ===================== MMA output MLP: vars[64]->128(relu)->16 + sigmoid ====
__global__ void __launch_bounds__(256) out_mma_kernel(
        const uint4* __restrict__ w1p, const float* __restrict__ b1,
        const uint4* __restrict__ w2p, const float* __restrict__ b2,
        float* __restrict__ outp, int rows) {
    int tid = threadIdx.x;
    int wid = tid >> 5;
    int lane = tid & 31;
    int m = lane & 3;
    int g = lane >> 2;

    int rbase = blockIdx.x * 128 + wid * 16;
    if (rbase >= rows) return;
    int r0 = rbase + g, r1 = rbase + g + 8;
    int rr0 = min(r0, rows - 1), rr1 = min(r1, rows - 1);

    float d1[16][4];
#pragma unroll
    for (int j = 0; j < 16; j++)
#pragma unroll
        for (int q = 0; q < 4; q++) d1[j][q] = 0.f;

#pragma unroll
    for (int t = 0; t < 4; t++) {
        int kc = t * 16 + 2 * m;
        float2 x0 = *(const float2*)&g_vars[(size_t)rr0 * 64 + kc];
        float2 x1 = *(const float2*)&g_vars[(size_t)rr1 * 64 + kc];
        float2 x2 = *(const float2*)&g_vars[(size_t)rr0 * 64 + kc + 8];
        float2 x3 = *(const float2*)&g_vars[(size_t)rr1 * 64 + kc + 8];
        u32 ah0, al0, ah1, al1, ah2, al2, ah3, al3;
        bfsplit2(x0.x, x0.y, ah0, al0);
        bfsplit2(x1.x, x1.y, ah1, al1);
        bfsplit2(x2.x, x2.y, ah2, al2);
        bfsplit2(x3.x, x3.y, ah3, al3);

        const uint4* wp = w1p + (size_t)(t * 16) * 32 + lane;
#pragma unroll
        for (int j = 0; j < 16; j++) {
            uint4 w = __ldg(&wp[j * 32]);
            mma_bf16(d1[j], ah0, ah1, ah2, ah3, w.x, w.y);
            mma_bf16(d1[j], ah0, ah1, ah2, ah3, w.z, w.w);
            mma_bf16(d1[j], al0, al1, al2, al3, w.x, w.y);
        }
    }

    float d2[2][4];
#pragma unroll
    for (int j = 0; j < 2; j++)
#pragma unroll
        for (int q = 0; q < 4; q++) d2[j][q] = 0.f;

#pragma unroll
    for (int t = 0; t < 8; t++) {
        float2 ba = *(const float2*)&b1[16 * t + 2 * m];
        float2 bb = *(const float2*)&b1[16 * t + 8 + 2 * m];
        float f0 = fmaxf(d1[2 * t][0] + ba.x, 0.f);
        float f1 = fmaxf(d1[2 * t][1] + ba.y, 0.f);
        float f2 = fmaxf(d1[2 * t][2] + ba.x, 0.f);
        float f3 = fmaxf(d1[2 * t][3] + ba.y, 0.f);
        float f4 = fmaxf(d1[2 * t + 1][0] + bb.x, 0.f);
        float f5 = fmaxf(d1[2 * t + 1][1] + bb.y, 0.f);
        float f6 = fmaxf(d1[2 * t + 1][2] + bb.x, 0.f);
        float f7 = fmaxf(d1[2 * t + 1][3] + bb.y, 0.f);
        u32 ah0, al0, ah1, al1, ah2, al2, ah3, al3;
        bfsplit2(f0, f1, ah0, al0);
        bfsplit2(f2, f3, ah1, al1);
        bfsplit2(f4, f5, ah2, al2);
        bfsplit2(f6, f7, ah3, al3);

        const uint4* wp = w2p + (size_t)(t * 2) * 32 + lane;
#pragma unroll
        for (int j = 0; j < 2; j++) {
            uint4 w = __ldg(&wp[j * 32]);
            mma_bf16(d2[j], ah0, ah1, ah2, ah3, w.x, w.y);
            mma_bf16(d2[j], ah0, ah1, ah2, ah3, w.z, w.w);
            mma_bf16(d2[j], al0, al1, al2, al3, w.x, w.y);
        }
    }

#pragma unroll
    for (int j = 0; j < 2; j++) {
        float2 b = *(const float2*)&b2[8 * j + 2 * m];
        if (r0 < rows) {
            float z0 = d2[j][0] + b.x;
            float z1 = d2[j][1] + b.y;
            *(float2*)&outp[(size_t)r0 * OUTB + 8 * j + 2 * m] =
                make_float2(1.f / (1.f + __expf(-z0)), 1.f / (1.f + __expf(-z1)));
        }
        if (r1 < rows) {
            float z2 = d2[j][2] + b.x;
            float z3 = d2[j][3] + b.y;
            *(float2*)&outp[(size_t)r1 * OUTB + 8 * j + 2 * m] =
                make_float2(1.f / (1.f + __expf(-z2)), 1.f / (1.f + __expf(-z3)));
        }
    }
}

// ===================== scalar prep kernel ===================================
__device__ __forceinline__ void mlp_layer2_64(const float* sbuf,
                                              const float* __restrict__ W2,
                                              const float* __restrict__ b2,
                                              float* __restrict__ outp,
                                              int row0, int rows, int lane) {
    float2 acc[4];
#pragma unroll
    for (int r = 0; r < 4; r++) acc[r] = make_float2(0.f, 0.f);

    for (int k = 0; k < 128; k += 4) {
        float4 hv[4];
#pragma unroll
        for (int r = 0; r < 4; r++) hv[r] = *(const float4*)&sbuf[r * 128 + k];
#pragma unroll
        for (int kk = 0; kk < 4; kk++) {
            float2 w = *(const float2*)&W2[(k + kk) * 64 + 2 * lane];
#pragma unroll
            for (int r = 0; r < 4; r++) {
                float hk = ((const float*)&hv[r])[kk];
                acc[r].x += hk * w.x;
                acc[r].y += hk * w.y;
            }
        }
    }
    float2 bb = *(const float2*)&b2[2 * lane];
#pragma unroll
    for (int r = 0; r < 4; r++) {
        if (row0 + r < rows) {
            *(float2*)&outp[(size_t)(row0 + r) * 64 + 2 * lane] =
                make_float2(acc[r].x + bb.x, acc[r].y + bb.y);
        }
    }
}

__global__ void __launch_bounds__(256) prep_kernel(
                            const float* __restrict__ cond,
                            const float* __restrict__ w1, const float* __restrict__ b1,
                            const float* __restrict__ w2, const float* __restrict__ b2,
                            int rows) {
    __shared__ float sbuf[8][512];
    int warp = threadIdx.x >> 5;
    int lane = threadIdx.x & 31;
    int row0 = (blockIdx.x * 8 + warp) * 4;
    if (row0 >= rows) return;
    float* sbf = sbuf[warp];

    float4 w = *(const float4*)&w1[4 * lane];
    float4 b = *(const float4*)&b1[4 * lane];
#pragma unroll
    for (int r = 0; r < 4; r++) {
        int row = min(row0 + r, rows - 1);
        float c = cond[row];
        float4 h;
        h.x = fmaxf(c * w.x + b.x, 0.f);
        h.y = fmaxf(c * w.y + b.y, 0.f);
        h.z = fmaxf(c * w.z + b.z, 0.f);
        h.w = fmaxf(c * w.w + b.w, 0.f);
        *(float4*)&sbf[r * 128 + 4 * lane] = h;
    }
    __syncwarp();
    mlp_layer2_64(sbf, w2, b2, g_cons, row0, rows, lane);
}

// ===================== launch ===============================================
extern "C" void kernel_launch(void* const* d_in, const int* in_sizes, int n_in,
                              void* d_out, int out_size) {
    const int*   row  = (const int*)  d_in[0];
    const int*   col  = (const int*)  d_in[1];
    const float* adj  = (const float*)d_in[2];
    const float* cond = (const float*)d_in[3];

    int nnz = in_sizes[0];
    int C   = in_sizes[3];
    int V   = out_size / OUTB;
    if (nnz > MAXNNZ) nnz = MAXNNZ;
    if (C > MAXC) C = MAXC;
    if (V > MAXV) V = MAXV;

    int w = 4;
    if (n_in >= 22 && in_sizes[4] == 1 && in_sizes[5] == 1) w = 6;
    const float* pc_w1 = (const float*)d_in[w + 0];
    const float* pc_b1 = (const float*)d_in[w + 1];
    const float* pc_w2 = (const float*)d_in[w + 2];
    const float* pc_b2 = (const float*)d_in[w + 3];
    const float* cu_w1 = (const float*)d_in[w + 4];
    const float* cu_b1 = (const float*)d_in[w + 5];
    const float* cu_w2 = (const float*)d_in[w + 6];
    const float* cu_b2 = (const float*)d_in[w + 7];
    const float* vu_w1 = (const float*)d_in[w + 8];
    const float* vu_b1 = (const float*)d_in[w + 9];
    const float* vu_w2 = (const float*)d_in[w + 10];
    const float* vu_b2 = (const float*)d_in[w + 11];
    const float* o_w1  = (const float*)d_in[w + 12];
    const float* o_b1  = (const float*)d_in[w + 13];
    const float* o_w2  = (const float*)d_in[w + 14];
    const float* o_b2  = (const float*)d_in[w + 15];

    float *p_vars, *p_cons, *p_v2c, *p_c2v;
    int   *p_offC, *p_offV;
    u64   *p_cscE, *p_csrE;
    u32   *p_w1cu, *p_w2cu, *p_w1vu, *p_w2vu, *p_w1o, *p_w2o;
    cudaGetSymbolAddress((void**)&p_vars,  g_vars);
    cudaGetSymbolAddress((void**)&p_cons,  g_cons);
    cudaGetSymbolAddress((void**)&p_v2c,   g_v2c);
    cudaGetSymbolAddress((void**)&p_c2v,   g_c2v);
    cudaGetSymbolAddress((void**)&p_offC,  g_offC);
    cudaGetSymbolAddress((void**)&p_offV,  g_offV);
    cudaGetSymbolAddress((void**)&p_cscE,  g_cscE);
    cudaGetSymbolAddress((void**)&p_csrE,  g_csrE);
    cudaGetSymbolAddress((void**)&p_w1cu,  g_w1p_cu);
    cudaGetSymbolAddress((void**)&p_w2cu,  g_w2p_cu);
    cudaGetSymbolAddress((void**)&p_w1vu,  g_w1p_vu);
    cudaGetSymbolAddress((void**)&p_w2vu,  g_w2p_vu);
    cudaGetSymbolAddress((void**)&p_w1o,   g_w1p_out);
    cudaGetSymbolAddress((void**)&p_w2o,   g_w2p_out);

    int maxCV = (C > V) ? C : V;

    zero_counts_kernel<<<(maxCV + 255) / 256, 256>>>(C, V);
    hist_kernel<<<(nnz + 2047) / 2048, 256>>>(row, col, nnz);
    scan_kernel<<<2, 1024>>>(C, V);
    fill_kernel<<<(nnz + 1023) / 1024, 256>>>(row, col, adj, nnz);
    init_vars_kernel<<<(V * FM + 255) / 256, 256>>>(V * FM);
    conv_w_kernel<<<64, 256>>>(cu_w1, cu_w2, p_w1cu, p_w2cu);
    conv_w_kernel<<<64, 256>>>(vu_w1, vu_w2, p_w1vu, p_w2vu);
    conv_w_out_kernel<<<32, 256>>>(o_w1, o_w2, p_w1o, p_w2o);
    prep_kernel<<<(C + 31) / 32, 256>>>(cond, pc_w1, pc_b1, pc_w2, pc_b2, C);

    int gC = (C + 127) / 128;
    int gV = (V + 127) / 128;
    for (int it = 0; it < 3; it++) {
        seg_gather_kernel<<<(C + 7) / 8, 256>>>(p_offC, p_cscE, p_vars, p_v2c, C);
        mlp_mma_kernel<<<gC, 256>>>(p_cons, p_v2c, p_cons,
                                    (const uint4*)p_w1cu, cu_b1, (const uint4*)p_w2cu, cu_b2, C);
        seg_gather_kernel<<<(V + 7) / 8, 256>>>(p_offV, p_csrE, p_cons, p_c2v, V);
        mlp_mma_kernel<<<gV, 256>>>(p_vars, p_c2v, p_vars,
                                    (const uint4*)p_w1vu, vu_b1, (const uint4*)p_w2vu, vu_b2, V);
    }

    out_mma_kernel<<<gV, 256>>>((const uint4*)p_w1o, o_b1, (const uint4*)p_w2o, o_b2,
                                (float*)d_out, V);
}